// round 1
// baseline (speedup 1.0000x reference)
#include <cuda_runtime.h>

#define NWIRE 480
#define NT    16
#define NN    150000
#define NE    1800000
#define NEG   0.2f

// ---- static device scratch (allocation-free rule: __device__ globals) ----
__device__ int   g_rowptr[NN + 1];
__device__ int   g_cursor[NN];
__device__ int   g_col[NE];
__device__ float g_rec1[NN * 24];   // per-node layer1 record: h[16], as0, as1, ad0, ad1, pad[4]  (96B)
__device__ float g_rec2[NN * 8];    // per-node layer2 record: h2[4], as, ad, pad[2]              (32B)

// ================= CSR build (topology is launch-invariant; built once per launch) ============

__global__ void k_zero() {
    int i = blockIdx.x * blockDim.x + threadIdx.x;
    if (i < NN) g_cursor[i] = 0;
}

__global__ void k_hist(const int* __restrict__ ei) {
    int e = blockIdx.x * blockDim.x + threadIdx.x;
    if (e < NE) atomicAdd(&g_cursor[ei[NE + e]], 1);
}

// single-block chunked exclusive scan over NN counts -> g_rowptr, and copy into g_cursor
__global__ void k_scan() {
    __shared__ int s[1024];
    const int chunk = (NN + 1023) / 1024;
    int t  = threadIdx.x;
    int lo = t * chunk;
    int hi = min(lo + chunk, NN);
    int sum = 0;
    for (int i = lo; i < hi; i++) sum += g_cursor[i];
    s[t] = sum;
    __syncthreads();
    for (int off = 1; off < 1024; off <<= 1) {
        int v = (t >= off) ? s[t - off] : 0;
        __syncthreads();
        s[t] += v;
        __syncthreads();
    }
    int run = s[t] - sum;  // exclusive prefix for this chunk
    for (int i = lo; i < hi; i++) {
        int c = g_cursor[i];
        g_rowptr[i] = run;
        g_cursor[i] = run;
        run += c;
    }
    if (t == 1023) g_rowptr[NN] = NE;
}

__global__ void k_fill(const int* __restrict__ ei) {
    int e = blockIdx.x * blockDim.x + threadIdx.x;
    if (e < NE) {
        int d   = ei[NE + e];
        int pos = atomicAdd(&g_cursor[d], 1);
        g_col[pos] = ei[e];  // src
    }
}

// ================= per-tick pipeline ============

// K1: gather wire triplet, x@W1 (12->16), per-node attention logits. Write packed 96B record.
__global__ void __launch_bounds__(256) k1_features(
    const float4* __restrict__ w1p, const float4* __restrict__ w2p, const float4* __restrict__ w3p,
    const int* __restrict__ idx,
    const float* __restrict__ W1, const float* __restrict__ a1s, const float* __restrict__ a1d,
    int t)
{
    __shared__ float sW[192], ss[16], sd[16];
    int tid = threadIdx.x;
    if (tid < 192) sW[tid] = W1[tid];
    else if (tid < 208) ss[tid - 192] = a1s[tid - 192];
    else if (tid < 224) sd[tid - 208] = a1d[tid - 208];
    __syncthreads();

    int n = blockIdx.x * blockDim.x + tid;
    if (n >= NN) return;

    int i0 = idx[3 * n], i1 = idx[3 * n + 1], i2 = idx[3 * n + 2];
    float4 x0 = w1p[t * NWIRE + i0];
    float4 x1 = w2p[t * NWIRE + i1];
    float4 x2 = w3p[t * NWIRE + i2];
    float x[12] = { x0.x, x0.y, x0.z, x0.w, x1.x, x1.y, x1.z, x1.w, x2.x, x2.y, x2.z, x2.w };

    float h[16];
#pragma unroll
    for (int j = 0; j < 16; j++) {
        float a = 0.f;
#pragma unroll
        for (int k = 0; k < 12; k++) a += x[k] * sW[k * 16 + j];
        h[j] = a;
    }
    float as0 = 0.f, as1 = 0.f, ad0 = 0.f, ad1 = 0.f;
#pragma unroll
    for (int d = 0; d < 8; d++) {
        as0 += h[d]     * ss[d];
        ad0 += h[d]     * sd[d];
        as1 += h[8 + d] * ss[8 + d];
        ad1 += h[8 + d] * sd[8 + d];
    }
    float4* o = (float4*)&g_rec1[n * 24];
    o[0] = make_float4(h[0],  h[1],  h[2],  h[3]);
    o[1] = make_float4(h[4],  h[5],  h[6],  h[7]);
    o[2] = make_float4(h[8],  h[9],  h[10], h[11]);
    o[3] = make_float4(h[12], h[13], h[14], h[15]);
    o[4] = make_float4(as0, as1, ad0, ad1);
}

// K2: layer-1 softmax-aggregate (thread per dst) + ELU + x@W2 (16->4) + layer-2 logits.
__global__ void __launch_bounds__(256) k2_agg1(
    const float* __restrict__ W2, const float* __restrict__ a2s, const float* __restrict__ a2d)
{
    __shared__ float sW[64], ss[4], sd[4];
    int tid = threadIdx.x;
    if (tid < 64) sW[tid] = W2[tid];
    if (tid < 4) { ss[tid] = a2s[tid]; sd[tid] = a2d[tid]; }
    __syncthreads();

    int n = blockIdx.x * blockDim.x + tid;
    if (n >= NN) return;

    const float4* rec = (const float4*)g_rec1;
    float4 mya = rec[n * 6 + 4];
    float ad0 = mya.z, ad1 = mya.w;

    int eb = g_rowptr[n], ee = g_rowptr[n + 1];
    float acc[16];
#pragma unroll
    for (int j = 0; j < 16; j++) acc[j] = 0.f;
    float den0 = 0.f, den1 = 0.f;

    for (int e = eb; e < ee; e++) {
        int s = g_col[e];
        const float4* r = rec + (size_t)s * 6;
        float4 aa = r[4];
        float4 h0 = r[0], h1 = r[1], h2 = r[2], h3 = r[3];
        float z0 = aa.x + ad0; z0 = z0 > 0.f ? z0 : NEG * z0;
        float z1 = aa.y + ad1; z1 = z1 > 0.f ? z1 : NEG * z1;
        float w0 = __expf(z0), w1 = __expf(z1);
        den0 += w0; den1 += w1;
        acc[0]  += w0 * h0.x; acc[1]  += w0 * h0.y; acc[2]  += w0 * h0.z; acc[3]  += w0 * h0.w;
        acc[4]  += w0 * h1.x; acc[5]  += w0 * h1.y; acc[6]  += w0 * h1.z; acc[7]  += w0 * h1.w;
        acc[8]  += w1 * h2.x; acc[9]  += w1 * h2.y; acc[10] += w1 * h2.z; acc[11] += w1 * h2.w;
        acc[12] += w1 * h3.x; acc[13] += w1 * h3.y; acc[14] += w1 * h3.z; acc[15] += w1 * h3.w;
    }

    float inv0 = 1.f / fmaxf(den0, 1e-16f);
    float inv1 = 1.f / fmaxf(den1, 1e-16f);
    float o[16];
#pragma unroll
    for (int j = 0; j < 8; j++) { o[j] = acc[j] * inv0; o[8 + j] = acc[8 + j] * inv1; }
#pragma unroll
    for (int j = 0; j < 16; j++) o[j] = o[j] > 0.f ? o[j] : (__expf(o[j]) - 1.f);   // ELU

    float h2o[4] = {0.f, 0.f, 0.f, 0.f};
#pragma unroll
    for (int j = 0; j < 16; j++) {
        float oj = o[j];
#pragma unroll
        for (int c = 0; c < 4; c++) h2o[c] += oj * sW[j * 4 + c];
    }
    float s2 = 0.f, d2 = 0.f;
#pragma unroll
    for (int c = 0; c < 4; c++) { s2 += h2o[c] * ss[c]; d2 += h2o[c] * sd[c]; }

    float4* w = (float4*)&g_rec2[n * 8];
    w[0] = make_float4(h2o[0], h2o[1], h2o[2], h2o[3]);
    w[1] = make_float4(s2, d2, 0.f, 0.f);
}

// K3: layer-2 softmax-aggregate + final MLP (4->1), write output.
__global__ void __launch_bounds__(256) k3_agg2(
    const float* __restrict__ mw, const float* __restrict__ mb,
    float* __restrict__ out, int t)
{
    int n = blockIdx.x * blockDim.x + threadIdx.x;
    if (n >= NN) return;

    const float4* rec = (const float4*)g_rec2;
    float ad = rec[n * 2 + 1].y;

    int eb = g_rowptr[n], ee = g_rowptr[n + 1];
    float a0 = 0.f, a1 = 0.f, a2 = 0.f, a3 = 0.f, den = 0.f;
    for (int e = eb; e < ee; e++) {
        int s = g_col[e];
        float4 h  = rec[(size_t)s * 2];
        float4 aa = rec[(size_t)s * 2 + 1];
        float z = aa.x + ad; z = z > 0.f ? z : NEG * z;
        float w = __expf(z);
        den += w;
        a0 += w * h.x; a1 += w * h.y; a2 += w * h.z; a3 += w * h.w;
    }
    float inv = 1.f / fmaxf(den, 1e-16f);
    float y = (a0 * mw[0] + a1 * mw[1] + a2 * mw[2] + a3 * mw[3]) * inv + mb[0];
    out[t * NN + n] = y;
}

// ================= launch ============

extern "C" void kernel_launch(void* const* d_in, const int* in_sizes, int n_in,
                              void* d_out, int out_size)
{
    const float* fw  = (const float*)d_in[0];
    const float* sw  = (const float*)d_in[1];
    const float* tw  = (const float*)d_in[2];
    const int*   idx = (const int*)  d_in[3];
    const int*   ei  = (const int*)  d_in[4];
    const float* W1  = (const float*)d_in[5];
    const float* a1s = (const float*)d_in[6];
    const float* a1d = (const float*)d_in[7];
    const float* W2  = (const float*)d_in[8];
    const float* a2s = (const float*)d_in[9];
    const float* a2d = (const float*)d_in[10];
    const float* mw  = (const float*)d_in[11];
    const float* mb  = (const float*)d_in[12];
    float* out = (float*)d_out;

    const int nb_n = (NN + 255) / 256;
    const int nb_e = (NE + 255) / 256;

    // CSR by dst (edge_index is the same for every tick/layer)
    k_zero<<<nb_n, 256>>>();
    k_hist<<<nb_e, 256>>>(ei);
    k_scan<<<1, 1024>>>();
    k_fill<<<nb_e, 256>>>(ei);

    for (int t = 0; t < NT; t++) {
        k1_features<<<nb_n, 256>>>((const float4*)fw, (const float4*)sw, (const float4*)tw,
                                   idx, W1, a1s, a1d, t);
        k2_agg1<<<nb_n, 256>>>(W2, a2s, a2d);
        k3_agg2<<<nb_n, 256>>>(mw, mb, out, t);
    }
}

// round 3
// speedup vs baseline: 1.7315x; 1.7315x over previous
#include <cuda_runtime.h>
#include <cuda_fp16.h>

#define NWIRE 480
#define NT    16
#define NN    150000
#define NE    1800000
#define NEG   0.2f

// ---- static device scratch ----
__device__ int    g_rowptr[NN + 1];
__device__ int    g_cursor[NN];
__device__ int    g_col[NE];
__device__ float4 g_rec1[NT * NN * 2];  // per (tick,node): h[16] fp16 packed = 32B = 1 L2 sector
__device__ float2 g_rec2[NT * NN];      // per (tick,node): h2[4] fp16 = 8B

// ================= CSR build (topology launch-invariant) =================

__global__ void k_zero() {
    int i = blockIdx.x * blockDim.x + threadIdx.x;
    if (i < NN) g_cursor[i] = 0;
}

__global__ void k_hist(const int* __restrict__ ei) {
    int e = blockIdx.x * blockDim.x + threadIdx.x;
    if (e < NE) atomicAdd(&g_cursor[ei[NE + e]], 1);
}

__global__ void k_scan() {
    __shared__ int s[1024];
    const int chunk = (NN + 1023) / 1024;
    int t  = threadIdx.x;
    int lo = t * chunk;
    int hi = min(lo + chunk, NN);
    int sum = 0;
    for (int i = lo; i < hi; i++) sum += g_cursor[i];
    s[t] = sum;
    __syncthreads();
    for (int off = 1; off < 1024; off <<= 1) {
        int v = (t >= off) ? s[t - off] : 0;
        __syncthreads();
        s[t] += v;
        __syncthreads();
    }
    int run = s[t] - sum;
    for (int i = lo; i < hi; i++) {
        int c = g_cursor[i];
        g_rowptr[i] = run;
        g_cursor[i] = run;
        run += c;
    }
    if (t == 1023) g_rowptr[NN] = NE;
}

__global__ void k_fill(const int* __restrict__ ei) {
    int e = blockIdx.x * blockDim.x + threadIdx.x;
    if (e < NE) {
        int d   = ei[NE + e];
        int pos = atomicAdd(&g_cursor[d], 1);
        g_col[pos] = ei[e];
    }
}

// ================= K1: features for ALL ticks (grid.y = tick) =================

__global__ void __launch_bounds__(256) k1_features(
    const float4* __restrict__ w1p, const float4* __restrict__ w2p, const float4* __restrict__ w3p,
    const int* __restrict__ idx, const float* __restrict__ W1)
{
    __shared__ float sW[192];
    int tid = threadIdx.x;
    if (tid < 192) sW[tid] = W1[tid];
    __syncthreads();

    int n = blockIdx.x * blockDim.x + tid;
    if (n >= NN) return;
    int t = blockIdx.y;

    int i0 = idx[3 * n], i1 = idx[3 * n + 1], i2 = idx[3 * n + 2];
    float4 x0 = w1p[t * NWIRE + i0];
    float4 x1 = w2p[t * NWIRE + i1];
    float4 x2 = w3p[t * NWIRE + i2];
    float x[12] = { x0.x, x0.y, x0.z, x0.w, x1.x, x1.y, x1.z, x1.w, x2.x, x2.y, x2.z, x2.w };

    float h[16];
#pragma unroll
    for (int j = 0; j < 16; j++) {
        float a = 0.f;
#pragma unroll
        for (int k = 0; k < 12; k++) a += x[k] * sW[k * 16 + j];
        h[j] = a;
    }

    float4 p0, p1;
    half2* ha = (half2*)&p0;
    half2* hb = (half2*)&p1;
#pragma unroll
    for (int j = 0; j < 4; j++) ha[j] = __floats2half2_rn(h[2 * j],     h[2 * j + 1]);
#pragma unroll
    for (int j = 0; j < 4; j++) hb[j] = __floats2half2_rn(h[8 + 2 * j], h[9 + 2 * j]);

    size_t base = ((size_t)t * NN + n) * 2;
    g_rec1[base]     = p0;
    g_rec1[base + 1] = p1;
}

// ================= K2: layer-1 softmax-aggregate + ELU + W2 =================

__device__ __forceinline__ void unpack16(const float4& p0, const float4& p1, float* f) {
    const half2* ha = (const half2*)&p0;
    const half2* hb = (const half2*)&p1;
#pragma unroll
    for (int j = 0; j < 4; j++) {
        float2 v = __half22float2(ha[j]);
        f[2 * j] = v.x; f[2 * j + 1] = v.y;
    }
#pragma unroll
    for (int j = 0; j < 4; j++) {
        float2 v = __half22float2(hb[j]);
        f[8 + 2 * j] = v.x; f[9 + 2 * j] = v.y;
    }
}

__global__ void __launch_bounds__(256) k2_agg1(
    const float* __restrict__ a1s, const float* __restrict__ a1d,
    const float* __restrict__ W2)
{
    __shared__ float ss[16], sd[16], sW[64];
    int tid = threadIdx.x;
    if (tid < 16) { ss[tid] = a1s[tid]; sd[tid] = a1d[tid]; }
    if (tid >= 32 && tid < 96) sW[tid - 32] = W2[tid - 32];
    __syncthreads();

    int n = blockIdx.x * blockDim.x + tid;
    if (n >= NN) return;
    int t = blockIdx.y;

    const float4* rec = g_rec1 + (size_t)t * NN * 2;

    // own h -> dst logits
    float hm[16];
    unpack16(rec[2 * n], rec[2 * n + 1], hm);
    float ad0 = 0.f, ad1 = 0.f;
#pragma unroll
    for (int d = 0; d < 8; d++) { ad0 += hm[d] * sd[d]; ad1 += hm[8 + d] * sd[8 + d]; }

    int eb = g_rowptr[n], ee = g_rowptr[n + 1];
    float acc[16];
#pragma unroll
    for (int j = 0; j < 16; j++) acc[j] = 0.f;
    float den0 = 0.f, den1 = 0.f;

    auto edge = [&](const float4& r0, const float4& r1) {
        float f[16];
        unpack16(r0, r1, f);
        float as0 = 0.f, as1 = 0.f;
#pragma unroll
        for (int d = 0; d < 8; d++) { as0 += f[d] * ss[d]; as1 += f[8 + d] * ss[8 + d]; }
        float z0 = as0 + ad0; z0 = z0 > 0.f ? z0 : NEG * z0;
        float z1 = as1 + ad1; z1 = z1 > 0.f ? z1 : NEG * z1;
        float w0 = __expf(z0), w1 = __expf(z1);
        den0 += w0; den1 += w1;
#pragma unroll
        for (int j = 0; j < 8; j++)  acc[j] += w0 * f[j];
#pragma unroll
        for (int j = 8; j < 16; j++) acc[j] += w1 * f[j];
    };

    int e = eb;
    for (; e + 2 <= ee; e += 2) {
        int s0 = g_col[e], s1 = g_col[e + 1];
        float4 r00 = rec[2 * s0], r01 = rec[2 * s0 + 1];
        float4 r10 = rec[2 * s1], r11 = rec[2 * s1 + 1];
        edge(r00, r01);
        edge(r10, r11);
    }
    if (e < ee) {
        int s0 = g_col[e];
        edge(rec[2 * s0], rec[2 * s0 + 1]);
    }

    float inv0 = 1.f / fmaxf(den0, 1e-16f);
    float inv1 = 1.f / fmaxf(den1, 1e-16f);
    float o[16];
#pragma unroll
    for (int j = 0; j < 8; j++) { o[j] = acc[j] * inv0; o[8 + j] = acc[8 + j] * inv1; }
#pragma unroll
    for (int j = 0; j < 16; j++) o[j] = o[j] > 0.f ? o[j] : (__expf(o[j]) - 1.f);  // ELU

    float h2o[4] = {0.f, 0.f, 0.f, 0.f};
#pragma unroll
    for (int j = 0; j < 16; j++) {
        float oj = o[j];
#pragma unroll
        for (int c = 0; c < 4; c++) h2o[c] += oj * sW[j * 4 + c];
    }

    float2 w;
    half2* hw = (half2*)&w;
    hw[0] = __floats2half2_rn(h2o[0], h2o[1]);
    hw[1] = __floats2half2_rn(h2o[2], h2o[3]);
    g_rec2[(size_t)t * NN + n] = w;
}

// ================= K3: layer-2 softmax-aggregate + final MLP =================

__global__ void __launch_bounds__(256) k3_agg2(
    const float* __restrict__ a2s, const float* __restrict__ a2d,
    const float* __restrict__ mw, const float* __restrict__ mb,
    float* __restrict__ out)
{
    __shared__ float ss[4], sd[4], sm[4], sb;
    int tid = threadIdx.x;
    if (tid < 4) { ss[tid] = a2s[tid]; sd[tid] = a2d[tid]; sm[tid] = mw[tid]; }
    if (tid == 4) sb = mb[0];
    __syncthreads();

    int n = blockIdx.x * blockDim.x + tid;
    if (n >= NN) return;
    int t = blockIdx.y;

    const float2* rec = g_rec2 + (size_t)t * NN;

    float2 me = rec[n];
    const half2* mh = (const half2*)&me;
    float2 m0 = __half22float2(mh[0]), m1 = __half22float2(mh[1]);
    float ad = m0.x * sd[0] + m0.y * sd[1] + m1.x * sd[2] + m1.y * sd[3];

    int eb = g_rowptr[n], ee = g_rowptr[n + 1];
    float a0 = 0.f, a1 = 0.f, a2 = 0.f, a3 = 0.f, den = 0.f;

    auto edge = [&](const float2& v) {
        const half2* hh = (const half2*)&v;
        float2 f0 = __half22float2(hh[0]), f1 = __half22float2(hh[1]);
        float as = f0.x * ss[0] + f0.y * ss[1] + f1.x * ss[2] + f1.y * ss[3];
        float z = as + ad; z = z > 0.f ? z : NEG * z;
        float w = __expf(z);
        den += w;
        a0 += w * f0.x; a1 += w * f0.y; a2 += w * f1.x; a3 += w * f1.y;
    };

    // unroll-by-4: batch independent record loads to raise MLP
    int e = eb;
    for (; e + 4 <= ee; e += 4) {
        int s0 = g_col[e], s1 = g_col[e + 1], s2 = g_col[e + 2], s3 = g_col[e + 3];
        float2 v0 = rec[s0], v1 = rec[s1], v2 = rec[s2], v3 = rec[s3];
        edge(v0); edge(v1); edge(v2); edge(v3);
    }
    for (; e < ee; e++) edge(rec[g_col[e]]);

    float inv = 1.f / fmaxf(den, 1e-16f);
    float y = (a0 * sm[0] + a1 * sm[1] + a2 * sm[2] + a3 * sm[3]) * inv + sb;
    out[(size_t)t * NN + n] = y;
}

// ================= launch =================

extern "C" void kernel_launch(void* const* d_in, const int* in_sizes, int n_in,
                              void* d_out, int out_size)
{
    const float* fw  = (const float*)d_in[0];
    const float* sw  = (const float*)d_in[1];
    const float* tw  = (const float*)d_in[2];
    const int*   idx = (const int*)  d_in[3];
    const int*   ei  = (const int*)  d_in[4];
    const float* W1  = (const float*)d_in[5];
    const float* a1s = (const float*)d_in[6];
    const float* a1d = (const float*)d_in[7];
    const float* W2  = (const float*)d_in[8];
    const float* a2s = (const float*)d_in[9];
    const float* a2d = (const float*)d_in[10];
    const float* mw  = (const float*)d_in[11];
    const float* mb  = (const float*)d_in[12];
    float* out = (float*)d_out;

    const int nb_n = (NN + 255) / 256;
    const int nb_e = (NE + 255) / 256;

    k_zero<<<nb_n, 256>>>();
    k_hist<<<nb_e, 256>>>(ei);
    k_scan<<<1, 1024>>>();
    k_fill<<<nb_e, 256>>>(ei);

    dim3 gn(nb_n, NT, 1);
    k1_features<<<gn, 256>>>((const float4*)fw, (const float4*)sw, (const float4*)tw, idx, W1);
    k2_agg1<<<gn, 256>>>(a1s, a1d, W2);
    k3_agg2<<<gn, 256>>>(a2s, a2d, mw, mb, out);
}